// round 8
// baseline (speedup 1.0000x reference)
#include <cuda_runtime.h>

// Static device scratch (no allocation allowed anywhere).
// Zero-initialized at module load; the epilogue kernel re-zeros it after
// reading, so every kernel_launch invocation (incl. graph replays) sees 0.
#define MAX_SEGS 8192
#define MAX_D    256
__device__ float g_accum[MAX_SEGS * MAX_D];   // 8 MB

// ---------------------------------------------------------------------------
// Main kernel: one block per (uniform row-chunk, 128-column half).
// grid = (ceil(n/R), D/128) sized so total blocks == 148*8 = one wave of
// IDENTICAL-size blocks -> no segment-length tail.
// 128 threads = 32 float4-lanes x 4 row-groups, 4-deep LDG.128 prefetch.
// Segment sums are order-independent (plain sum of exp), so each thread
// accumulates locally and atomically flushes on the (rare, warp-uniform)
// segment change within its chunk.
// ---------------------------------------------------------------------------
#define CHUNK_MAX 512   // upper bound on R for the smem stage

__device__ __forceinline__ void acc4(float4 v, float a[4]) {
    a[0] += __expf(v.x);
    a[1] += __expf(v.y);
    a[2] += __expf(v.z);
    a[3] += __expf(v.w);
}

__global__ __launch_bounds__(128, 8)
void pool_sum_kernel(const float* __restrict__ feats,
                     const void* __restrict__ batch,
                     int n, int D, int G, int R) {
    __shared__ int sh_is64;
    __shared__ int sm_seg[CHUNK_MAX];

    // Dtype probe (warp 0): int64 values in [0,G) => odd 32-bit words are all
    // zero high-halves; any nonzero sampled odd word => int32.
    if (threadIdx.x < 32) {
        const int* b32 = (const int*)batch;
        int limit = n < 8192 ? n : 8192;
        int step  = limit / 32; if (step < 2) step = 2;
        int idx   = threadIdx.x * step + 1;
        if (idx >= limit) idx = limit - 1;
        idx |= 1;
        if (idx >= limit) idx -= 2;
        int v = (idx >= 0) ? b32[idx] : 0;
        unsigned nz = __ballot_sync(0xFFFFFFFFu, v != 0);
        if (threadIdx.x == 0) sh_is64 = (nz == 0) ? 1 : 0;
    }
    __syncthreads();
    const int is64 = sh_is64;

    const int r0  = blockIdx.x * R;
    int cnt = n - r0;
    if (cnt > R) cnt = R;
    if (cnt <= 0) return;

    // Stage this chunk's segment ids in smem (clamped for safety).
    for (int i = threadIdx.x; i < cnt; i += 128) {
        int sg = is64 ? (int)((const long long*)batch)[r0 + i]
                      : ((const int*)batch)[r0 + i];
        if (sg < 0) sg = 0;
        if (sg > G - 1) sg = G - 1;
        sm_seg[i] = sg;
    }
    __syncthreads();

    const int colblk = blockIdx.y * 128;
    const int lane   = threadIdx.x & 31;
    const int rg     = threadIdx.x >> 5;            // row group 0..3
    const int c4     = (colblk >> 2) + lane;        // float4 index in row
    const int col0   = colblk + lane * 4;           // first of 4 owned columns

    float a[4] = {0.f, 0.f, 0.f, 0.f};
    int acc_seg = (rg < cnt) ? sm_seg[rg] : -1;

    const size_t rstride = (size_t)(D >> 2);
    const float4* __restrict__ p =
        (const float4*)feats + (size_t)(r0 + rg) * rstride + c4;

#define CONSUME(v, lr)                                                        \
    do {                                                                      \
        int _sg = sm_seg[(lr)];                                               \
        if (_sg != acc_seg) {  /* warp-uniform, ~2x per chunk */              \
            float* dst = &g_accum[(size_t)acc_seg * D + col0];                \
            atomicAdd(dst + 0, a[0]); atomicAdd(dst + 1, a[1]);               \
            atomicAdd(dst + 2, a[2]); atomicAdd(dst + 3, a[3]);               \
            a[0] = a[1] = a[2] = a[3] = 0.f;                                  \
            acc_seg = _sg;                                                    \
        }                                                                     \
        acc4((v), a);                                                         \
    } while (0)

    int lr = rg;                                    // local rows: rg, rg+4, ...
    if (lr + 12 < cnt) {
        float4 a0 = __ldg(p);
        float4 a1 = __ldg(p +  4 * rstride);
        float4 a2 = __ldg(p +  8 * rstride);
        float4 a3 = __ldg(p + 12 * rstride);
        p += 16 * rstride;
        lr += 16;
        for (; lr + 12 < cnt; lr += 16) {
            float4 b0 = __ldg(p);
            float4 b1 = __ldg(p +  4 * rstride);
            float4 b2 = __ldg(p +  8 * rstride);
            float4 b3 = __ldg(p + 12 * rstride);
            p += 16 * rstride;
            CONSUME(a0, lr - 16);
            CONSUME(a1, lr - 12);
            CONSUME(a2, lr -  8);
            CONSUME(a3, lr -  4);
            a0 = b0; a1 = b1; a2 = b2; a3 = b3;
        }
        CONSUME(a0, lr - 16);
        CONSUME(a1, lr - 12);
        CONSUME(a2, lr -  8);
        CONSUME(a3, lr -  4);
    }
    for (; lr < cnt; lr += 4) {
        float4 v = __ldg(p);
        p += 4 * rstride;
        CONSUME(v, lr);
    }
#undef CONSUME

    // Final flush.
    if (acc_seg >= 0) {
        float* dst = &g_accum[(size_t)acc_seg * D + col0];
        atomicAdd(dst + 0, a[0]); atomicAdd(dst + 1, a[1]);
        atomicAdd(dst + 2, a[2]); atomicAdd(dst + 3, a[3]);
    }
}

// ---------------------------------------------------------------------------
// Epilogue: out = log(clip(S, 1e-12)) and re-zero the scratch so the next
// invocation (graph replay) starts from a clean accumulator. Empty segments
// (S = 0) clamp to log(1e-12), matching the reference semantics.
// ---------------------------------------------------------------------------
__global__ void log_reset_kernel(float* __restrict__ out, int total4) {
    int i = blockIdx.x * blockDim.x + threadIdx.x;
    if (i >= total4) return;
    float4* acc4p = (float4*)g_accum;
    float4  S = acc4p[i];
    float4  o;
    o.x = __logf(fmaxf(S.x, 1e-12f));
    o.y = __logf(fmaxf(S.y, 1e-12f));
    o.z = __logf(fmaxf(S.z, 1e-12f));
    o.w = __logf(fmaxf(S.w, 1e-12f));
    ((float4*)out)[i] = o;
    acc4p[i] = make_float4(0.f, 0.f, 0.f, 0.f);
}

// ---------------------------------------------------------------------------
// Inputs (metadata order): feats f32 [N*D], batch int [N], num_segments.
// ---------------------------------------------------------------------------
extern "C" void kernel_launch(void* const* d_in, const int* in_sizes, int n_in,
                              void* d_out, int out_size) {
    const float* feats = (const float*)d_in[0];
    const void*  batch = d_in[1];

    const int n = in_sizes[1];                // rows (200000)
    const int D = in_sizes[0] / n;            // features (256)
    const int G = out_size / D;               // segments (512)

    // One wave of identical blocks: chunks * (D/128) <= 148*8 = 1184.
    const int colhalves = D / 128;            // 2
    const int max_chunks = 1184 / colhalves;  // 592
    int R = (n + max_chunks - 1) / max_chunks;
    if (R < 16) R = 16;
    if (R > CHUNK_MAX) R = CHUNK_MAX;         // safety for the smem stage
    const int nchunks = (n + R - 1) / R;

    dim3 grid(nchunks, colhalves);
    pool_sum_kernel<<<grid, 128>>>(feats, batch, n, D, G, R);

    const int total4 = out_size / 4;
    log_reset_kernel<<<(total4 + 255) / 256, 256>>>((float*)d_out, total4);
}